// round 2
// baseline (speedup 1.0000x reference)
#include <cuda_runtime.h>
#include <cuda_bf16.h>

#define N_NODES 10000
#define N_EDGES 320000
#define N_GRAPHS 64
#define FEAT 256
#define TOT_EDGES (N_EDGES + N_NODES)

// ---------------- scratch (static device globals; no allocation) ----------------
__device__ int   g_cnt[N_NODES];
__device__ int   g_rowptr[N_NODES + 1];
__device__ int   g_pos[N_NODES];
__device__ float g_dinv[N_NODES];
__device__ __align__(128) int   g_col[TOT_EDGES];
__device__ __align__(128) float g_w[TOT_EDGES];
__device__ float g_s1[N_NODES];
__device__ __align__(128) float g_out1[N_NODES * FEAT];
__device__ __align__(128) float g_h2[N_NODES * FEAT];
__device__ __align__(128) float g_out2[N_NODES * FEAT];
__device__ __align__(128) float g_pool[N_GRAPHS * FEAT];
__device__ int   g_gstart[N_GRAPHS + 1];

// ---------------- CSR build ----------------
__global__ void k_init_cnt() {
    int i = blockIdx.x * blockDim.x + threadIdx.x;
    if (i < N_NODES) g_cnt[i] = 1;  // self-loop
}

__global__ void k_count_edges(const int* __restrict__ ei) {
    int e = blockIdx.x * blockDim.x + threadIdx.x;
    if (e < N_EDGES) {
        int dst = ei[N_EDGES + e];
        atomicAdd(&g_cnt[dst], 1);
    }
}

__global__ void k_scan() {
    // single block, 1024 threads, exclusive scan of g_cnt -> g_rowptr
    __shared__ int sh[1024];
    int tid = threadIdx.x;
    const int per = (N_NODES + 1023) / 1024;
    int start = tid * per;
    int end = min(start + per, N_NODES);
    int s = 0;
    for (int i = start; i < end; i++) s += g_cnt[i];
    sh[tid] = s;
    __syncthreads();
    for (int off = 1; off < 1024; off <<= 1) {
        int v = (tid >= off) ? sh[tid - off] : 0;
        __syncthreads();
        sh[tid] += v;
        __syncthreads();
    }
    int run = sh[tid] - s;  // exclusive prefix
    for (int i = start; i < end; i++) { g_rowptr[i] = run; run += g_cnt[i]; }
    if (end == N_NODES && start < N_NODES) g_rowptr[N_NODES] = run;
}

__global__ void k_dinv_pos() {
    int i = blockIdx.x * blockDim.x + threadIdx.x;
    if (i < N_NODES) {
        g_dinv[i] = rsqrtf((float)g_cnt[i]);
        g_pos[i] = g_rowptr[i];
    }
}

__global__ void k_fill_edges(const int* __restrict__ ei) {
    int e = blockIdx.x * blockDim.x + threadIdx.x;
    if (e < N_EDGES) {
        int src = ei[e];
        int dst = ei[N_EDGES + e];
        int slot = atomicAdd(&g_pos[dst], 1);
        g_col[slot] = src;
        g_w[slot] = g_dinv[src];
    }
}

__global__ void k_fill_self() {
    int i = blockIdx.x * blockDim.x + threadIdx.x;
    if (i < N_NODES) {
        int slot = atomicAdd(&g_pos[i], 1);
        g_col[slot] = i;
        g_w[slot] = g_dinv[i];
    }
}

// ---------------- layer 1 (collapsed to scalar) ----------------
__global__ void k_layer1_agg(const float* __restrict__ x) {
    int warp = (blockIdx.x * blockDim.x + threadIdx.x) >> 5;
    int lane = threadIdx.x & 31;
    if (warp >= N_NODES) return;
    int s0 = g_rowptr[warp], s1 = g_rowptr[warp + 1];
    float acc = 0.f;
    for (int s = s0 + lane; s < s1; s += 32)
        acc += g_w[s] * x[g_col[s]];
    #pragma unroll
    for (int off = 16; off > 0; off >>= 1)
        acc += __shfl_down_sync(0xFFFFFFFF, acc, off);
    if (lane == 0) g_s1[warp] = g_dinv[warp] * acc;
}

__global__ void k_out1(const float* __restrict__ W1, const float* __restrict__ b1) {
    int node = blockIdx.x;
    int c = threadIdx.x;
    float v = g_s1[node] * W1[c] + b1[c];
    g_out1[node * FEAT + c] = fmaxf(v, 0.f);
}

// ---------------- SGEMM: g_h2 = g_out1 @ W2   (M=10000, N=K=256) ----------------
#define BM 64
#define BN 64
#define BK 16
#define TM 4
#define TN 4
__global__ __launch_bounds__(256) void k_sgemm(const float* __restrict__ B) {
    __shared__ float As[BM][BK + 1];
    __shared__ float Bs[BK][BN];
    const float* A = g_out1;
    float* C = g_h2;
    int tx = threadIdx.x;
    int block_row = blockIdx.y * BM;
    int block_col = blockIdx.x * BN;
    int tr = tx / (BN / TN);   // 0..15
    int tc = tx % (BN / TN);   // 0..15
    float acc[TM][TN];
    #pragma unroll
    for (int m = 0; m < TM; m++)
        #pragma unroll
        for (int n = 0; n < TN; n++) acc[m][n] = 0.f;

    int arow = tx / 4;                 // 0..63
    int acol = (tx % 4) * 4;           // 0,4,8,12
    int brow = tx / 16;                // 0..15
    int bcol = (tx % 16) * 4;          // 0..60

    for (int k0 = 0; k0 < FEAT; k0 += BK) {
        int gar = block_row + arow;
        float4 av = make_float4(0.f, 0.f, 0.f, 0.f);
        if (gar < N_NODES)
            av = *(const float4*)(A + (size_t)gar * FEAT + k0 + acol);
        As[arow][acol + 0] = av.x;
        As[arow][acol + 1] = av.y;
        As[arow][acol + 2] = av.z;
        As[arow][acol + 3] = av.w;
        float4 bv = *(const float4*)(B + (size_t)(k0 + brow) * FEAT + block_col + bcol);
        Bs[brow][bcol + 0] = bv.x;
        Bs[brow][bcol + 1] = bv.y;
        Bs[brow][bcol + 2] = bv.z;
        Bs[brow][bcol + 3] = bv.w;
        __syncthreads();
        #pragma unroll
        for (int kk = 0; kk < BK; kk++) {
            float a[TM], b[TN];
            #pragma unroll
            for (int m = 0; m < TM; m++) a[m] = As[tr * TM + m][kk];
            #pragma unroll
            for (int n = 0; n < TN; n++) b[n] = Bs[kk][tc * TN + n];
            #pragma unroll
            for (int m = 0; m < TM; m++)
                #pragma unroll
                for (int n = 0; n < TN; n++)
                    acc[m][n] += a[m] * b[n];
        }
        __syncthreads();
    }
    #pragma unroll
    for (int m = 0; m < TM; m++) {
        int row = block_row + tr * TM + m;
        if (row < N_NODES) {
            #pragma unroll
            for (int n = 0; n < TN; n++)
                C[(size_t)row * FEAT + block_col + tc * TN + n] = acc[m][n];
        }
    }
}

// ---------------- layer 2 gather: out2 = relu(dinv[d]*sum(w*h2[src]) + b2) ----------------
__global__ __launch_bounds__(256) void k_gather2(const float* __restrict__ b2) {
    int warp = (blockIdx.x * blockDim.x + threadIdx.x) >> 5;
    int lane = threadIdx.x & 31;
    if (warp >= N_NODES) return;
    int s0 = g_rowptr[warp], s1 = g_rowptr[warp + 1];
    float acc[8] = {0.f, 0.f, 0.f, 0.f, 0.f, 0.f, 0.f, 0.f};
    const float* h = g_h2;
    int s = s0;
    for (; s + 1 < s1; s += 2) {
        int c0 = g_col[s], c1 = g_col[s + 1];
        float w0 = g_w[s], w1 = g_w[s + 1];
        const float4* r0 = (const float4*)(h + (size_t)c0 * FEAT + lane * 8);
        const float4* r1 = (const float4*)(h + (size_t)c1 * FEAT + lane * 8);
        float4 a0 = r0[0], d0 = r0[1];
        float4 a1 = r1[0], d1 = r1[1];
        acc[0] += w0 * a0.x; acc[1] += w0 * a0.y; acc[2] += w0 * a0.z; acc[3] += w0 * a0.w;
        acc[4] += w0 * d0.x; acc[5] += w0 * d0.y; acc[6] += w0 * d0.z; acc[7] += w0 * d0.w;
        acc[0] += w1 * a1.x; acc[1] += w1 * a1.y; acc[2] += w1 * a1.z; acc[3] += w1 * a1.w;
        acc[4] += w1 * d1.x; acc[5] += w1 * d1.y; acc[6] += w1 * d1.z; acc[7] += w1 * d1.w;
    }
    if (s < s1) {
        int c0 = g_col[s];
        float w0 = g_w[s];
        const float4* r0 = (const float4*)(h + (size_t)c0 * FEAT + lane * 8);
        float4 a0 = r0[0], d0 = r0[1];
        acc[0] += w0 * a0.x; acc[1] += w0 * a0.y; acc[2] += w0 * a0.z; acc[3] += w0 * a0.w;
        acc[4] += w0 * d0.x; acc[5] += w0 * d0.y; acc[6] += w0 * d0.z; acc[7] += w0 * d0.w;
    }
    float dd = g_dinv[warp];
    int cbase = lane * 8;
    float4 o0, o1;
    o0.x = fmaxf(dd * acc[0] + b2[cbase + 0], 0.f);
    o0.y = fmaxf(dd * acc[1] + b2[cbase + 1], 0.f);
    o0.z = fmaxf(dd * acc[2] + b2[cbase + 2], 0.f);
    o0.w = fmaxf(dd * acc[3] + b2[cbase + 3], 0.f);
    o1.x = fmaxf(dd * acc[4] + b2[cbase + 4], 0.f);
    o1.y = fmaxf(dd * acc[5] + b2[cbase + 5], 0.f);
    o1.z = fmaxf(dd * acc[6] + b2[cbase + 6], 0.f);
    o1.w = fmaxf(dd * acc[7] + b2[cbase + 7], 0.f);
    float4* out = (float4*)(g_out2 + (size_t)warp * FEAT + cbase);
    out[0] = o0;
    out[1] = o1;
}

// ---------------- mean pool ----------------
__global__ void k_graph_bounds(const int* __restrict__ batch) {
    int g = threadIdx.x;  // 0..64
    if (g > N_GRAPHS) return;
    int lo = 0, hi = N_NODES;
    while (lo < hi) {
        int mid = (lo + hi) >> 1;
        if (batch[mid] < g) lo = mid + 1; else hi = mid;
    }
    g_gstart[g] = lo;
}

__global__ void k_pool() {
    int g = blockIdx.x;
    int c = threadIdx.x;
    int s = g_gstart[g], e = g_gstart[g + 1];
    float acc = 0.f;
    for (int i = s; i < e; i++) acc += g_out2[(size_t)i * FEAT + c];
    int n = e - s;
    g_pool[g * FEAT + c] = acc / (float)max(n, 1);
}

// ---------------- MLP head (one block per graph) ----------------
__global__ __launch_bounds__(256) void k_mlp(
    const float* __restrict__ W3, const float* __restrict__ b3,
    const float* __restrict__ W4, const float* __restrict__ b4,
    const float* __restrict__ W5, const float* __restrict__ b5,
    const float* __restrict__ W6, const float* __restrict__ b6,
    const float* __restrict__ W7, const float* __restrict__ b7,
    float* __restrict__ y)
{
    int g = blockIdx.x;
    int t = threadIdx.x;
    __shared__ float v0[256];
    __shared__ float v1[128];
    __shared__ float v2[128];
    __shared__ float v3[64];
    __shared__ float v4[32];
    v0[t] = g_pool[g * FEAT + t];
    __syncthreads();
    if (t < 128) {
        float a = b3[t];
        #pragma unroll 4
        for (int k = 0; k < 256; k++) a += v0[k] * W3[k * 128 + t];
        v1[t] = fmaxf(a, 0.f);
    }
    __syncthreads();
    if (t < 128) {
        float a = b4[t];
        #pragma unroll 4
        for (int k = 0; k < 128; k++) a += v1[k] * W4[k * 128 + t];
        v2[t] = fmaxf(a, 0.f);
    }
    __syncthreads();
    if (t < 64) {
        float a = b5[t];
        #pragma unroll 4
        for (int k = 0; k < 128; k++) a += v2[k] * W5[k * 64 + t];
        v3[t] = fmaxf(a, 0.f);
    }
    __syncthreads();
    if (t < 32) {
        float a = b6[t];
        #pragma unroll 4
        for (int k = 0; k < 64; k++) a += v3[k] * W6[k * 32 + t];
        v4[t] = fmaxf(a, 0.f);
    }
    __syncthreads();
    if (t < 32) {
        float p = v4[t] * W7[t];
        #pragma unroll
        for (int off = 16; off > 0; off >>= 1)
            p += __shfl_down_sync(0xFFFFFFFF, p, off);
        if (t == 0) y[g] = p + b7[0];
    }
}

// ---------------- launch ----------------
extern "C" void kernel_launch(void* const* d_in, const int* in_sizes, int n_in,
                              void* d_out, int out_size) {
    const float* x     = (const float*)d_in[0];
    const int*   ei    = (const int*)d_in[1];
    const int*   batch = (const int*)d_in[2];
    const float* W1 = (const float*)d_in[3];
    const float* b1 = (const float*)d_in[4];
    const float* W2 = (const float*)d_in[5];
    const float* b2 = (const float*)d_in[6];
    const float* W3 = (const float*)d_in[7];
    const float* b3 = (const float*)d_in[8];
    const float* W4 = (const float*)d_in[9];
    const float* b4 = (const float*)d_in[10];
    const float* W5 = (const float*)d_in[11];
    const float* b5 = (const float*)d_in[12];
    const float* W6 = (const float*)d_in[13];
    const float* b6 = (const float*)d_in[14];
    const float* W7 = (const float*)d_in[15];
    const float* b7 = (const float*)d_in[16];
    float* y = (float*)d_out;

    const int nb_nodes = (N_NODES + 255) / 256;
    const int nb_edges = (N_EDGES + 255) / 256;
    const int nb_warp_nodes = (N_NODES * 32 + 255) / 256;

    k_init_cnt<<<nb_nodes, 256>>>();
    k_count_edges<<<nb_edges, 256>>>(ei);
    k_scan<<<1, 1024>>>();
    k_dinv_pos<<<nb_nodes, 256>>>();
    k_fill_edges<<<nb_edges, 256>>>(ei);
    k_fill_self<<<nb_nodes, 256>>>();

    k_layer1_agg<<<nb_warp_nodes, 256>>>(x);
    k_out1<<<N_NODES, 256>>>(W1, b1);

    dim3 gemm_grid(FEAT / BN, (N_NODES + BM - 1) / BM);
    k_sgemm<<<gemm_grid, 256>>>(W2);

    k_gather2<<<nb_warp_nodes, 256>>>(b2);

    k_graph_bounds<<<1, N_GRAPHS + 1>>>(batch);
    k_pool<<<N_GRAPHS, 256>>>();
    k_mlp<<<N_GRAPHS, 256>>>(W3, b3, W4, b4, W5, b5, W6, b6, W7, b7, y);
}